// round 16
// baseline (speedup 1.0000x reference)
#include <cuda_runtime.h>
#include <cuda_bf16.h>
#include <cstdint>

#define NN 50000
#define EE 800000
#define NEG 0.2f

typedef unsigned long long u64;

// ---------------- scratch (static device globals; no allocation) ----------------
__device__ __align__(16) float    g_gl1[NN * 128];
__device__ __align__(16) float    g_gr1[NN * 128];
__device__ __align__(16) float    g_gl2[NN * 32];
__device__ __align__(16) float    g_gr2[NN * 32];
// bf16-split staging for the tensor-core GEMMs
__device__ __align__(16) __nv_bfloat16 g_xhi[NN * 128];
__device__ __align__(16) __nv_bfloat16 g_xlo[NN * 128];
__device__ __align__(16) __nv_bfloat16 g_h1hi[NN * 128];   // elu(h1) split (from agg1)
__device__ __align__(16) __nv_bfloat16 g_h1lo[NN * 128];
__device__ __align__(16) __nv_bfloat16 g_wthi[2 * 128 * 128];  // layer1 W^T per mat
__device__ __align__(16) __nv_bfloat16 g_wtlo[2 * 128 * 128];
__device__ __align__(16) __nv_bfloat16 g_wt2hi[2 * 32 * 128];  // layer2 W^T per mat
__device__ __align__(16) __nv_bfloat16 g_wt2lo[2 * 32 * 128];
// CSR by dst
__device__ unsigned g_cnt[NN];          // statically zero; scan re-zeroes each call
__device__ unsigned g_rowstart[NN + 1];
__device__ unsigned g_cursor[NN];
__device__ int      g_csrc[EE];

// ---------------- warp-MMA helpers (base-target: sm_80+, compiles for sm_103) -------
__device__ __forceinline__ uint32_t smem_u32(const void* p) {
    uint32_t a;
    asm("{ .reg .u64 t; cvta.to.shared.u64 t, %1; cvt.u32.u64 %0, t; }"
        : "=r"(a) : "l"(p));
    return a;
}
__device__ __forceinline__ void ldm_x4(uint32_t a[4], uint32_t addr) {
    asm volatile("ldmatrix.sync.aligned.m8n8.x4.shared.b16 {%0,%1,%2,%3}, [%4];"
        : "=r"(a[0]), "=r"(a[1]), "=r"(a[2]), "=r"(a[3]) : "r"(addr));
}
__device__ __forceinline__ void ldm_x2(uint32_t b[2], uint32_t addr) {
    asm volatile("ldmatrix.sync.aligned.m8n8.x2.shared.b16 {%0,%1}, [%2];"
        : "=r"(b[0]), "=r"(b[1]) : "r"(addr));
}
__device__ __forceinline__ void mma_bf16(float c[4], const uint32_t a[4],
                                         const uint32_t b[2]) {
    asm volatile(
        "mma.sync.aligned.m16n8k16.row.col.f32.bf16.bf16.f32 "
        "{%0,%1,%2,%3}, {%4,%5,%6,%7}, {%8,%9}, {%0,%1,%2,%3};"
        : "+f"(c[0]), "+f"(c[1]), "+f"(c[2]), "+f"(c[3])
        : "r"(a[0]), "r"(a[1]), "r"(a[2]), "r"(a[3]), "r"(b[0]), "r"(b[1]));
}
__device__ __forceinline__ uint32_t pack_bf2(float a, float b) {
    return (uint32_t)__bfloat16_as_ushort(__float2bfloat16(a))
         | ((uint32_t)__bfloat16_as_ushort(__float2bfloat16(b)) << 16);
}

// ---------------- prep: fp32 -> bf16 hi/lo split ----------------
__global__ void convert_x_kernel(const float* __restrict__ x) {
    int i = blockIdx.x * blockDim.x + threadIdx.x;       // 4 elems per thread
    if (i >= NN * 32) return;
    float4 v = reinterpret_cast<const float4*>(x)[i];
    float h0 = __bfloat162float(__float2bfloat16(v.x));
    float h1 = __bfloat162float(__float2bfloat16(v.y));
    float h2 = __bfloat162float(__float2bfloat16(v.z));
    float h3 = __bfloat162float(__float2bfloat16(v.w));
    uint2 hw, lw;
    hw.x = pack_bf2(v.x, v.y);
    hw.y = pack_bf2(v.z, v.w);
    lw.x = pack_bf2(v.x - h0, v.y - h1);
    lw.y = pack_bf2(v.z - h2, v.w - h3);
    reinterpret_cast<uint2*>(g_xhi)[i] = hw;
    reinterpret_cast<uint2*>(g_xlo)[i] = lw;
}
// converts layer-1 W^T (2*128*128) AND layer-2 W^T (2*32*128) in one launch
__global__ void convert_w_kernel(const float* __restrict__ Wl1f,
                                 const float* __restrict__ Wr1f,
                                 const float* __restrict__ Wl2f,
                                 const float* __restrict__ Wr2f) {
    int i = blockIdx.x * blockDim.x + threadIdx.x;
    if (i < 2 * 128 * 128) {
        int mat = i >> 14;
        int r   = i & 16383;
        int nn  = r >> 7;
        int k   = r & 127;
        float v = (mat ? Wr1f : Wl1f)[k * 128 + nn];
        float h = __bfloat162float(__float2bfloat16(v));
        g_wthi[i] = __float2bfloat16(v);
        g_wtlo[i] = __float2bfloat16(v - h);
    } else if (i < 2 * 128 * 128 + 2 * 32 * 128) {
        int j   = i - 2 * 128 * 128;
        int mat = j >> 12;                 // 4096 per matrix
        int r   = j & 4095;
        int nn  = r >> 7;
        int k   = r & 127;
        float v = (mat ? Wr2f : Wl2f)[k * 32 + nn];
        float h = __bfloat162float(__float2bfloat16(v));
        g_wt2hi[j] = __float2bfloat16(v);
        g_wt2lo[j] = __float2bfloat16(v - h);
    }
}

// ---------------- layer-1 GEMM via mma.sync bf16-split, reg double-buffered ---------
// grid (782, 2): 64 rows x 128 cols of mat = blockIdx.y. 256 threads (8 warps).
// Warp tile 32x32. Fragments for step ks+1 prefetched while ks's MMAs issue.
__global__ __launch_bounds__(256, 2) void gemm1_mma_kernel(
    int n, const float* __restrict__ bl, const float* __restrict__ br)
{
    constexpr int PITCH   = 272;                 // bytes per row (17 x 16B)
    constexpr int A_TILE  = 64 * PITCH;          // 17408
    constexpr int B_TILE  = 128 * PITCH;         // 34816
    constexpr int OFF_AHI = 0;
    constexpr int OFF_ALO = A_TILE;
    constexpr int OFF_BHI = 2 * A_TILE;
    constexpr int OFF_BLO = 2 * A_TILE + B_TILE;

    extern __shared__ char sm[];
    const uint32_t sbase = smem_u32(sm);
    const int tid  = threadIdx.x;
    const int wid  = tid >> 5;
    const int lane = tid & 31;
    const int mat  = blockIdx.y;
    const int row0 = blockIdx.x * 64;

    // fill A tiles (hi, lo): 64 rows x 16 uint4
    {
        const uint4* xh = reinterpret_cast<const uint4*>(g_xhi);
        const uint4* xl = reinterpret_cast<const uint4*>(g_xlo);
        for (int i = tid; i < 64 * 16; i += 256) {
            int r = i >> 4, c = i & 15;
            int gr = row0 + r;
            if (gr >= n) gr = n - 1;
            *reinterpret_cast<uint4*>(sm + OFF_AHI + r * PITCH + c * 16) = xh[gr * 16 + c];
            *reinterpret_cast<uint4*>(sm + OFF_ALO + r * PITCH + c * 16) = xl[gr * 16 + c];
        }
        // one matrix = 128*128 bf16 = 2048 uint4
        const uint4* wh = reinterpret_cast<const uint4*>(g_wthi) + mat * 2048;
        const uint4* wl = reinterpret_cast<const uint4*>(g_wtlo) + mat * 2048;
        for (int i = tid; i < 128 * 16; i += 256) {
            int r = i >> 4, c = i & 15;
            *reinterpret_cast<uint4*>(sm + OFF_BHI + r * PITCH + c * 16) = wh[r * 16 + c];
            *reinterpret_cast<uint4*>(sm + OFF_BLO + r * PITCH + c * 16) = wl[r * 16 + c];
        }
    }
    __syncthreads();

    const int mbase = (wid >> 2) * 32;
    const int nbase = (wid & 3) * 32;

    float acc[2][4][4];
#pragma unroll
    for (int mt = 0; mt < 2; mt++)
#pragma unroll
        for (int nt = 0; nt < 4; nt++)
#pragma unroll
            for (int q = 0; q < 4; q++) acc[mt][nt][q] = 0.f;

    const int arow  = lane & 15;
    const int akoff = (lane >> 4) << 4;
    const int brow  = lane & 7;
    const int bkoff = ((lane >> 3) & 1) << 4;
    const uint32_t abase = sbase + OFF_AHI + (mbase + arow) * PITCH + akoff;
    const uint32_t bbase = sbase + OFF_BHI + (nbase + brow) * PITCH + bkoff;

    uint32_t ah[2][2][4], al[2][2][4], bh[2][4][2], bo[2][4][2];

    auto load_frags = [&](int ks, int buf) {
        const int kb = ks * 32;
#pragma unroll
        for (int mt = 0; mt < 2; mt++) {
            uint32_t addr = abase + mt * 16 * PITCH + kb;
            ldm_x4(ah[buf][mt], addr);
            ldm_x4(al[buf][mt], addr + (OFF_ALO - OFF_AHI));
        }
#pragma unroll
        for (int nt = 0; nt < 4; nt++) {
            uint32_t addr = bbase + nt * 8 * PITCH + kb;
            ldm_x2(bh[buf][nt], addr);
            ldm_x2(bo[buf][nt], addr + (OFF_BLO - OFF_BHI));
        }
    };

    load_frags(0, 0);
#pragma unroll
    for (int ks = 0; ks < 8; ++ks) {
        const int cur = ks & 1;
        if (ks < 7) load_frags(ks + 1, cur ^ 1);
#pragma unroll
        for (int mt = 0; mt < 2; mt++) {
#pragma unroll
            for (int nt = 0; nt < 4; nt++) {
                mma_bf16(acc[mt][nt], ah[cur][mt], bh[cur][nt]);
                mma_bf16(acc[mt][nt], ah[cur][mt], bo[cur][nt]);
                mma_bf16(acc[mt][nt], al[cur][mt], bh[cur][nt]);
            }
        }
    }

    const float* __restrict__ b = mat ? br : bl;
    float* __restrict__ C = mat ? g_gr1 : g_gl1;
    const int rql = lane >> 2;
    const int cql = (lane & 3) * 2;
#pragma unroll
    for (int mt = 0; mt < 2; mt++) {
        int r0 = row0 + mbase + mt * 16 + rql;
        int r1 = r0 + 8;
#pragma unroll
        for (int nt = 0; nt < 4; nt++) {
            int col = nbase + nt * 8 + cql;
            float2 bv = *reinterpret_cast<const float2*>(b + col);
            if (r0 < n) {
                float2 v = make_float2(acc[mt][nt][0] + bv.x, acc[mt][nt][1] + bv.y);
                *reinterpret_cast<float2*>(C + r0 * 128 + col) = v;
            }
            if (r1 < n) {
                float2 v = make_float2(acc[mt][nt][2] + bv.x, acc[mt][nt][3] + bv.y);
                *reinterpret_cast<float2*>(C + r1 * 128 + col) = v;
            }
        }
    }
}

// ---------------- layer-2 GEMM via mma.sync bf16-split (N=32) -----------------------
__global__ __launch_bounds__(256) void gemm2_mma_kernel(
    int n, const float* __restrict__ bl, const float* __restrict__ br)
{
    constexpr int PITCH   = 272;
    constexpr int A_TILE  = 128 * PITCH;         // 34816
    constexpr int B_TILE  = 32 * PITCH;          // 8704
    constexpr int OFF_AHI = 0;
    constexpr int OFF_ALO = A_TILE;
    constexpr int OFF_BHI = 2 * A_TILE;
    constexpr int OFF_BLO = 2 * A_TILE + B_TILE;

    extern __shared__ char sm[];
    const uint32_t sbase = smem_u32(sm);
    const int tid  = threadIdx.x;
    const int wid  = tid >> 5;
    const int lane = tid & 31;
    const int mat  = blockIdx.y;
    const int row0 = blockIdx.x * 128;

    {
        const uint4* xh = reinterpret_cast<const uint4*>(g_h1hi);
        const uint4* xl = reinterpret_cast<const uint4*>(g_h1lo);
        for (int i = tid; i < 128 * 16; i += 256) {
            int r = i >> 4, c = i & 15;
            int gr = row0 + r;
            if (gr >= n) gr = n - 1;
            *reinterpret_cast<uint4*>(sm + OFF_AHI + r * PITCH + c * 16) = xh[gr * 16 + c];
            *reinterpret_cast<uint4*>(sm + OFF_ALO + r * PITCH + c * 16) = xl[gr * 16 + c];
        }
        const uint4* wh = reinterpret_cast<const uint4*>(g_wt2hi) + mat * 512;
        const uint4* wl = reinterpret_cast<const uint4*>(g_wt2lo) + mat * 512;
        for (int i = tid; i < 32 * 16; i += 256) {
            int r = i >> 4, c = i & 15;
            *reinterpret_cast<uint4*>(sm + OFF_BHI + r * PITCH + c * 16) = wh[r * 16 + c];
            *reinterpret_cast<uint4*>(sm + OFF_BLO + r * PITCH + c * 16) = wl[r * 16 + c];
        }
    }
    __syncthreads();

    float acc[4][4];
#pragma unroll
    for (int nt = 0; nt < 4; nt++)
#pragma unroll
        for (int q = 0; q < 4; q++) acc[nt][q] = 0.f;

    const int arow  = lane & 15;
    const int akoff = (lane >> 4) << 4;
    const int brow  = lane & 7;
    const int bkoff = ((lane >> 3) & 1) << 4;

#pragma unroll
    for (int ks = 0; ks < 8; ++ks) {
        const int kb = ks * 32;
        uint32_t ah[4], al[4];
        uint32_t addr = sbase + OFF_AHI + (wid * 16 + arow) * PITCH + kb + akoff;
        ldm_x4(ah, addr);
        ldm_x4(al, addr + (OFF_ALO - OFF_AHI));
        uint32_t bh[4][2], bo[4][2];
#pragma unroll
        for (int nt = 0; nt < 4; nt++) {
            uint32_t baddr = sbase + OFF_BHI + (nt * 8 + brow) * PITCH + kb + bkoff;
            ldm_x2(bh[nt], baddr);
            ldm_x2(bo[nt], baddr + (OFF_BLO - OFF_BHI));
        }
#pragma unroll
        for (int nt = 0; nt < 4; nt++) {
            mma_bf16(acc[nt], ah, bh[nt]);
            mma_bf16(acc[nt], ah, bo[nt]);
            mma_bf16(acc[nt], al, bh[nt]);
        }
    }

    const float* __restrict__ b = mat ? br : bl;
    float* __restrict__ C = mat ? g_gr2 : g_gl2;
    const int rql = lane >> 2;
    const int cql = (lane & 3) * 2;
    int r0 = row0 + wid * 16 + rql;
    int r1 = r0 + 8;
#pragma unroll
    for (int nt = 0; nt < 4; nt++) {
        int col = nt * 8 + cql;
        float2 bv = *reinterpret_cast<const float2*>(b + col);
        if (r0 < n) {
            float2 v = make_float2(acc[nt][0] + bv.x, acc[nt][1] + bv.y);
            *reinterpret_cast<float2*>(C + r0 * 32 + col) = v;
        }
        if (r1 < n) {
            float2 v = make_float2(acc[nt][2] + bv.x, acc[nt][3] + bv.y);
            *reinterpret_cast<float2*>(C + r1 * 32 + col) = v;
        }
    }
}

// ---------------- CSR build ----------------
__global__ void csr_hist_kernel(const int* __restrict__ ei) {
    int i = blockIdx.x * blockDim.x + threadIdx.x;
    if (i < EE) atomicAdd(&g_cnt[ei[EE + i]], 1u);
}
__global__ __launch_bounds__(1024) void csr_scan_kernel() {
    __shared__ unsigned s[1024];
    const int T = 1024;
    const int CH = (NN + T - 1) / T;
    int t = threadIdx.x;
    int base = t * CH;
    unsigned sum = 0;
    for (int i = 0; i < CH; i++) {
        int j = base + i;
        if (j < NN) sum += g_cnt[j];
    }
    s[t] = sum;
    __syncthreads();
    for (int off = 1; off < T; off <<= 1) {
        unsigned u = (t >= off) ? s[t - off] : 0u;
        __syncthreads();
        s[t] += u;
        __syncthreads();
    }
    unsigned run = s[t] - sum;
    for (int i = 0; i < CH; i++) {
        int j = base + i;
        if (j < NN) {
            unsigned c = g_cnt[j];
            g_cnt[j] = 0u;
            g_rowstart[j] = run;
            g_cursor[j]   = run;
            run += c;
        }
    }
    if (t == T - 1) g_rowstart[NN] = run;
}
__global__ void csr_fill_kernel(const int* __restrict__ ei) {
    int i = blockIdx.x * blockDim.x + threadIdx.x;
    if (i < EE) {
        int d = ei[EE + i];
        unsigned pos = atomicAdd(&g_cursor[d], 1u);
        g_csrc[pos] = ei[i];
    }
}

// ---------------- layer 1: fused attention aggregation (warp per dst, depth-2) -------
// Leaky-relu via fmaxf(v, NEG*v) (valid for NEG in (0,1)); h1 emitted as bf16 hi/lo.
__global__ __launch_bounds__(256) void agg1_kernel(const float* __restrict__ att,
                                                   const float* __restrict__ bias) {
    const int lane = threadIdx.x & 31;
    const int d = blockIdx.x * (blockDim.x >> 5) + (threadIdx.x >> 5);
    if (d >= NN) return;

    const float4* __restrict__ gl4 = reinterpret_cast<const float4*>(g_gl1);
    const float4  grd = reinterpret_cast<const float4*>(g_gr1)[d * 32 + lane];
    const float4  at  = reinterpret_cast<const float4*>(att)[lane];

    float4 acc = make_float4(0.f, 0.f, 0.f, 0.f);
    float  den = 0.f;

    const unsigned start = g_rowstart[d];
    const unsigned deg   = g_rowstart[d + 1] - start;

    int s1 = (deg > 0) ? g_csrc[start]     : d;
    int s2 = (deg > 1) ? g_csrc[start + 1] : d;
    float4 gcur  = gl4[d  * 32 + lane];
    float4 gnext = gl4[s1 * 32 + lane];

    for (unsigned j = 0; j <= deg; ++j) {
        float4 gnn = gl4[s2 * 32 + lane];
        s2 = (j + 3 <= deg) ? g_csrc[start + j + 2] : d;

        float m0 = gcur.x + grd.x; m0 = fmaxf(m0, NEG * m0);
        float m1 = gcur.y + grd.y; m1 = fmaxf(m1, NEG * m1);
        float m2 = gcur.z + grd.z; m2 = fmaxf(m2, NEG * m2);
        float m3 = gcur.w + grd.w; m3 = fmaxf(m3, NEG * m3);
        float p = at.x * m0 + at.y * m1 + at.z * m2 + at.w * m3;
        p += __shfl_xor_sync(0xffffffffu, p, 1);
        p += __shfl_xor_sync(0xffffffffu, p, 2);
        p += __shfl_xor_sync(0xffffffffu, p, 4);
        float w = __expf(p);
        acc.x += w * gcur.x;
        acc.y += w * gcur.y;
        acc.z += w * gcur.z;
        acc.w += w * gcur.w;
        den += w;

        gcur = gnext;
        gnext = gnn;
    }

    const float inv = 1.f / den;
    const float4 b = reinterpret_cast<const float4*>(bias)[lane];
    float v0 = acc.x * inv + b.x; v0 = (v0 > 0.f) ? v0 : expm1f(v0);
    float v1 = acc.y * inv + b.y; v1 = (v1 > 0.f) ? v1 : expm1f(v1);
    float v2 = acc.z * inv + b.z; v2 = (v2 > 0.f) ? v2 : expm1f(v2);
    float v3 = acc.w * inv + b.w; v3 = (v3 > 0.f) ? v3 : expm1f(v3);

    float h0 = __bfloat162float(__float2bfloat16(v0));
    float h1 = __bfloat162float(__float2bfloat16(v1));
    float h2 = __bfloat162float(__float2bfloat16(v2));
    float h3 = __bfloat162float(__float2bfloat16(v3));
    uint2 hw, lw;
    hw.x = pack_bf2(v0, v1);
    hw.y = pack_bf2(v2, v3);
    lw.x = pack_bf2(v0 - h0, v1 - h1);
    lw.y = pack_bf2(v2 - h2, v3 - h3);
    reinterpret_cast<uint2*>(g_h1hi)[d * 32 + lane] = hw;
    reinterpret_cast<uint2*>(g_h1lo)[d * 32 + lane] = lw;
}

// ---------------- layer 2: aggregation, 4 dsts per warp (8 lanes / dst) -------------
__global__ __launch_bounds__(256) void agg2_kernel(const float* __restrict__ att,
                                                   const float* __restrict__ bias,
                                                   float* __restrict__ out) {
    const int lane = threadIdx.x & 31;
    const int grp  = lane >> 3;
    const int lg   = lane & 7;
    const int wid  = blockIdx.x * (blockDim.x >> 5) + (threadIdx.x >> 5);
    int d = wid * 4 + grp;
    const bool dvalid = (d < NN);
    if (d >= NN) d = NN - 1;

    const float4* __restrict__ gl4 = reinterpret_cast<const float4*>(g_gl2);
    const float4 grd  = reinterpret_cast<const float4*>(g_gr2)[d * 8 + lg];
    const float4 at   = reinterpret_cast<const float4*>(att)[lg];

    const unsigned start = g_rowstart[d];
    const unsigned deg   = dvalid ? (g_rowstart[d + 1] - start) : 0u;

    unsigned mdeg = deg;
#pragma unroll
    for (int off = 8; off < 32; off <<= 1) {
        unsigned o = __shfl_xor_sync(0xffffffffu, mdeg, off);
        mdeg = (o > mdeg) ? o : mdeg;
    }

    float4 acc = make_float4(0.f, 0.f, 0.f, 0.f);
    float  den = 0.f;

    int snext = (deg > 0) ? g_csrc[start] : d;
    float4 g = gl4[d * 8 + lg];

    for (unsigned j = 0; j <= mdeg; ++j) {
        float4 gc = g;
        int snn = (j + 2 <= deg) ? g_csrc[start + j + 1] : d;
        g = gl4[snext * 8 + lg];
        snext = snn;

        float m0 = gc.x + grd.x; m0 = fmaxf(m0, NEG * m0);
        float m1 = gc.y + grd.y; m1 = fmaxf(m1, NEG * m1);
        float m2 = gc.z + grd.z; m2 = fmaxf(m2, NEG * m2);
        float m3 = gc.w + grd.w; m3 = fmaxf(m3, NEG * m3);
        float p = at.x * m0 + at.y * m1 + at.z * m2 + at.w * m3;
        p += __shfl_xor_sync(0xffffffffu, p, 1);
        p += __shfl_xor_sync(0xffffffffu, p, 2);
        p += __shfl_xor_sync(0xffffffffu, p, 4);
        float w = (j <= deg) ? __expf(p) : 0.f;
        acc.x += w * gc.x;
        acc.y += w * gc.y;
        acc.z += w * gc.z;
        acc.w += w * gc.w;
        den += w;
    }

    if (dvalid) {
        const float inv = 1.f / den;
        const float4 b = reinterpret_cast<const float4*>(bias)[lg];
        reinterpret_cast<float4*>(out)[d * 8 + lg] =
            make_float4(acc.x * inv + b.x, acc.y * inv + b.y,
                        acc.z * inv + b.z, acc.w * inv + b.w);
    }
}

// ---------------- launch ----------------
extern "C" void kernel_launch(void* const* d_in, const int* in_sizes, int n_in,
                              void* d_out, int out_size) {
    const float* x    = (const float*)d_in[0];
    const int*   ei   = (const int*)d_in[1];
    const float* Wl1  = (const float*)d_in[2];
    const float* bl1  = (const float*)d_in[3];
    const float* Wr1  = (const float*)d_in[4];
    const float* br1  = (const float*)d_in[5];
    const float* att1 = (const float*)d_in[6];
    const float* bias1= (const float*)d_in[7];
    const float* Wl2  = (const float*)d_in[8];
    const float* bl2  = (const float*)d_in[9];
    const float* Wr2  = (const float*)d_in[10];
    const float* br2  = (const float*)d_in[11];
    const float* att2 = (const float*)d_in[12];
    const float* bias2= (const float*)d_in[13];
    float* out = (float*)d_out;

    const int smem1 = 2 * (64 * 272) + 2 * (128 * 272);   // 104448 -> 2 blocks/SM
    const int smem2 = 2 * (128 * 272) + 2 * (32 * 272);   // 87040  -> 2 blocks/SM
    cudaFuncSetAttribute(gemm1_mma_kernel,
                         cudaFuncAttributeMaxDynamicSharedMemorySize, smem1);
    cudaFuncSetAttribute(gemm2_mma_kernel,
                         cudaFuncAttributeMaxDynamicSharedMemorySize, smem2);

    // slots 1-3: converts + hist; slot 4: gemm1_mma (PROFILED)
    convert_x_kernel<<<(NN * 32 + 255) / 256, 256>>>(x);
    convert_w_kernel<<<(2 * 128 * 128 + 2 * 32 * 128 + 255) / 256, 256>>>(
        Wl1, Wr1, Wl2, Wr2);
    csr_hist_kernel<<<(EE + 255) / 256, 256>>>(ei);
    gemm1_mma_kernel<<<dim3((NN + 63) / 64, 2), 256, smem1>>>(NN, bl1, br1);
    csr_scan_kernel<<<1, 1024>>>();
    csr_fill_kernel<<<(EE + 255) / 256, 256>>>(ei);

    agg1_kernel<<<(NN + 7) / 8, 256>>>(att1, bias1);

    gemm2_mma_kernel<<<dim3((NN + 127) / 128, 2), 256, smem2>>>(NN, bl2, br2);
    agg2_kernel<<<(NN + 31) / 32, 256>>>(att2, bias2, out);
}

// round 17
// speedup vs baseline: 1.1286x; 1.1286x over previous
#include <cuda_runtime.h>
#include <cuda_bf16.h>
#include <cstdint>

#define NN 50000
#define EE 800000
#define NEG 0.2f

typedef unsigned long long u64;

// ---------------- scratch (static device globals; no allocation) ----------------
__device__ __align__(16) float    g_gl1[NN * 128];
__device__ __align__(16) float    g_gr1[NN * 128];
__device__ __align__(16) float    g_gl2[NN * 32];
__device__ __align__(16) float    g_gr2[NN * 32];
// bf16-split staging for the tensor-core GEMMs
__device__ __align__(16) __nv_bfloat16 g_xhi[NN * 128];
__device__ __align__(16) __nv_bfloat16 g_xlo[NN * 128];
__device__ __align__(16) __nv_bfloat16 g_h1hi[NN * 128];   // elu(h1) split (from agg1)
__device__ __align__(16) __nv_bfloat16 g_h1lo[NN * 128];
__device__ __align__(16) __nv_bfloat16 g_wthi[2 * 128 * 128];  // layer1 W^T per mat
__device__ __align__(16) __nv_bfloat16 g_wtlo[2 * 128 * 128];
__device__ __align__(16) __nv_bfloat16 g_wt2hi[2 * 32 * 128];  // layer2 W^T per mat
__device__ __align__(16) __nv_bfloat16 g_wt2lo[2 * 32 * 128];
// CSR by dst
__device__ unsigned g_cnt[NN];          // statically zero; scan re-zeroes each call
__device__ unsigned g_rowstart[NN + 1];
__device__ unsigned g_rank[EE];         // within-dst rank from hist's atomicAdd
__device__ int      g_csrc[EE];

// ---------------- warp-MMA helpers (base-target: sm_80+, compiles for sm_103) -------
__device__ __forceinline__ uint32_t smem_u32(const void* p) {
    uint32_t a;
    asm("{ .reg .u64 t; cvta.to.shared.u64 t, %1; cvt.u32.u64 %0, t; }"
        : "=r"(a) : "l"(p));
    return a;
}
__device__ __forceinline__ void ldm_x4(uint32_t a[4], uint32_t addr) {
    asm volatile("ldmatrix.sync.aligned.m8n8.x4.shared.b16 {%0,%1,%2,%3}, [%4];"
        : "=r"(a[0]), "=r"(a[1]), "=r"(a[2]), "=r"(a[3]) : "r"(addr));
}
__device__ __forceinline__ void ldm_x2(uint32_t b[2], uint32_t addr) {
    asm volatile("ldmatrix.sync.aligned.m8n8.x2.shared.b16 {%0,%1}, [%2];"
        : "=r"(b[0]), "=r"(b[1]) : "r"(addr));
}
__device__ __forceinline__ void mma_bf16(float c[4], const uint32_t a[4],
                                         const uint32_t b[2]) {
    asm volatile(
        "mma.sync.aligned.m16n8k16.row.col.f32.bf16.bf16.f32 "
        "{%0,%1,%2,%3}, {%4,%5,%6,%7}, {%8,%9}, {%0,%1,%2,%3};"
        : "+f"(c[0]), "+f"(c[1]), "+f"(c[2]), "+f"(c[3])
        : "r"(a[0]), "r"(a[1]), "r"(a[2]), "r"(a[3]), "r"(b[0]), "r"(b[1]));
}
__device__ __forceinline__ uint32_t pack_bf2(float a, float b) {
    return (uint32_t)__bfloat16_as_ushort(__float2bfloat16(a))
         | ((uint32_t)__bfloat16_as_ushort(__float2bfloat16(b)) << 16);
}

// ---------------- fused prep: convert_x | (hist + convert_w) ------------------------
// grid (6250, 2), 256 threads. y==0: x -> bf16 hi/lo. y==1: edge histogram (+rank)
// and W1/W2 -> bf16 hi/lo transposed (first blocks also handle W).
__global__ void prep_kernel(const float* __restrict__ x,
                            const int* __restrict__ ei,
                            const float* __restrict__ Wl1f,
                            const float* __restrict__ Wr1f,
                            const float* __restrict__ Wl2f,
                            const float* __restrict__ Wr2f) {
    int i = blockIdx.x * blockDim.x + threadIdx.x;
    if (blockIdx.y == 0) {
        if (i >= NN * 32) return;
        float4 v = reinterpret_cast<const float4*>(x)[i];
        float h0 = __bfloat162float(__float2bfloat16(v.x));
        float h1 = __bfloat162float(__float2bfloat16(v.y));
        float h2 = __bfloat162float(__float2bfloat16(v.z));
        float h3 = __bfloat162float(__float2bfloat16(v.w));
        uint2 hw, lw;
        hw.x = pack_bf2(v.x, v.y);
        hw.y = pack_bf2(v.z, v.w);
        lw.x = pack_bf2(v.x - h0, v.y - h1);
        lw.y = pack_bf2(v.z - h2, v.w - h3);
        reinterpret_cast<uint2*>(g_xhi)[i] = hw;
        reinterpret_cast<uint2*>(g_xlo)[i] = lw;
    } else {
        // edge histogram with rank capture
        if (i < EE) {
            int d = ei[EE + i];
            g_rank[i] = atomicAdd(&g_cnt[d], 1u);
        }
        // weight conversion (first 40960 threads of this plane)
        if (i < 2 * 128 * 128) {
            int mat = i >> 14;
            int r   = i & 16383;
            int nn  = r >> 7;
            int k   = r & 127;
            float v = (mat ? Wr1f : Wl1f)[k * 128 + nn];
            float h = __bfloat162float(__float2bfloat16(v));
            g_wthi[i] = __float2bfloat16(v);
            g_wtlo[i] = __float2bfloat16(v - h);
            if (i < 2 * 32 * 128) {
                int mat2 = i >> 12;
                int r2   = i & 4095;
                int nn2  = r2 >> 7;
                int k2   = r2 & 127;
                float v2 = (mat2 ? Wr2f : Wl2f)[k2 * 32 + nn2];
                float h2 = __bfloat162float(__float2bfloat16(v2));
                g_wt2hi[i] = __float2bfloat16(v2);
                g_wt2lo[i] = __float2bfloat16(v2 - h2);
            }
        }
    }
}

// ---------------- layer-1 GEMM via mma.sync bf16-split (round-15 proven form) -------
// grid (782, 2): 64 rows x 128 cols of mat = blockIdx.y. 256 threads (8 warps).
__global__ __launch_bounds__(256) void gemm1_mma_kernel(
    int n, const float* __restrict__ bl, const float* __restrict__ br)
{
    constexpr int PITCH   = 272;
    constexpr int A_TILE  = 64 * PITCH;
    constexpr int B_TILE  = 128 * PITCH;
    constexpr int OFF_AHI = 0;
    constexpr int OFF_ALO = A_TILE;
    constexpr int OFF_BHI = 2 * A_TILE;
    constexpr int OFF_BLO = 2 * A_TILE + B_TILE;

    extern __shared__ char sm[];
    const uint32_t sbase = smem_u32(sm);
    const int tid  = threadIdx.x;
    const int wid  = tid >> 5;
    const int lane = tid & 31;
    const int mat  = blockIdx.y;
    const int row0 = blockIdx.x * 64;

    {
        const uint4* xh = reinterpret_cast<const uint4*>(g_xhi);
        const uint4* xl = reinterpret_cast<const uint4*>(g_xlo);
        for (int i = tid; i < 64 * 16; i += 256) {
            int r = i >> 4, c = i & 15;
            int gr = row0 + r;
            if (gr >= n) gr = n - 1;
            *reinterpret_cast<uint4*>(sm + OFF_AHI + r * PITCH + c * 16) = xh[gr * 16 + c];
            *reinterpret_cast<uint4*>(sm + OFF_ALO + r * PITCH + c * 16) = xl[gr * 16 + c];
        }
        const uint4* wh = reinterpret_cast<const uint4*>(g_wthi) + mat * 2048;
        const uint4* wl = reinterpret_cast<const uint4*>(g_wtlo) + mat * 2048;
        for (int i = tid; i < 128 * 16; i += 256) {
            int r = i >> 4, c = i & 15;
            *reinterpret_cast<uint4*>(sm + OFF_BHI + r * PITCH + c * 16) = wh[r * 16 + c];
            *reinterpret_cast<uint4*>(sm + OFF_BLO + r * PITCH + c * 16) = wl[r * 16 + c];
        }
    }
    __syncthreads();

    const int mbase = (wid >> 2) * 32;
    const int nbase = (wid & 3) * 32;

    float acc[2][4][4];
#pragma unroll
    for (int mt = 0; mt < 2; mt++)
#pragma unroll
        for (int nt = 0; nt < 4; nt++)
#pragma unroll
            for (int q = 0; q < 4; q++) acc[mt][nt][q] = 0.f;

    const int arow  = lane & 15;
    const int akoff = (lane >> 4) << 4;
    const int brow  = lane & 7;
    const int bkoff = ((lane >> 3) & 1) << 4;

    for (int ks = 0; ks < 8; ++ks) {
        const int kb = ks * 32;
        uint32_t ah[2][4], al[2][4];
#pragma unroll
        for (int mt = 0; mt < 2; mt++) {
            uint32_t addr = sbase + OFF_AHI + (mbase + mt * 16 + arow) * PITCH + kb + akoff;
            ldm_x4(ah[mt], addr);
            ldm_x4(al[mt], addr + (OFF_ALO - OFF_AHI));
        }
        uint32_t bh[4][2], bo[4][2];
#pragma unroll
        for (int nt = 0; nt < 4; nt++) {
            uint32_t addr = sbase + OFF_BHI + (nbase + nt * 8 + brow) * PITCH + kb + bkoff;
            ldm_x2(bh[nt], addr);
            ldm_x2(bo[nt], addr + (OFF_BLO - OFF_BHI));
        }
#pragma unroll
        for (int mt = 0; mt < 2; mt++) {
#pragma unroll
            for (int nt = 0; nt < 4; nt++) {
                mma_bf16(acc[mt][nt], ah[mt], bh[nt]);
                mma_bf16(acc[mt][nt], ah[mt], bo[nt]);
                mma_bf16(acc[mt][nt], al[mt], bh[nt]);
            }
        }
    }

    const float* __restrict__ b = mat ? br : bl;
    float* __restrict__ C = mat ? g_gr1 : g_gl1;
    const int rql = lane >> 2;
    const int cql = (lane & 3) * 2;
#pragma unroll
    for (int mt = 0; mt < 2; mt++) {
        int r0 = row0 + mbase + mt * 16 + rql;
        int r1 = r0 + 8;
#pragma unroll
        for (int nt = 0; nt < 4; nt++) {
            int col = nbase + nt * 8 + cql;
            float2 bv = *reinterpret_cast<const float2*>(b + col);
            if (r0 < n) {
                float2 v = make_float2(acc[mt][nt][0] + bv.x, acc[mt][nt][1] + bv.y);
                *reinterpret_cast<float2*>(C + r0 * 128 + col) = v;
            }
            if (r1 < n) {
                float2 v = make_float2(acc[mt][nt][2] + bv.x, acc[mt][nt][3] + bv.y);
                *reinterpret_cast<float2*>(C + r1 * 128 + col) = v;
            }
        }
    }
}

// ---------------- layer-2 GEMM via mma.sync bf16-split (N=32) -----------------------
__global__ __launch_bounds__(256) void gemm2_mma_kernel(
    int n, const float* __restrict__ bl, const float* __restrict__ br)
{
    constexpr int PITCH   = 272;
    constexpr int A_TILE  = 128 * PITCH;
    constexpr int B_TILE  = 32 * PITCH;
    constexpr int OFF_AHI = 0;
    constexpr int OFF_ALO = A_TILE;
    constexpr int OFF_BHI = 2 * A_TILE;
    constexpr int OFF_BLO = 2 * A_TILE + B_TILE;

    extern __shared__ char sm[];
    const uint32_t sbase = smem_u32(sm);
    const int tid  = threadIdx.x;
    const int wid  = tid >> 5;
    const int lane = tid & 31;
    const int mat  = blockIdx.y;
    const int row0 = blockIdx.x * 128;

    {
        const uint4* xh = reinterpret_cast<const uint4*>(g_h1hi);
        const uint4* xl = reinterpret_cast<const uint4*>(g_h1lo);
        for (int i = tid; i < 128 * 16; i += 256) {
            int r = i >> 4, c = i & 15;
            int gr = row0 + r;
            if (gr >= n) gr = n - 1;
            *reinterpret_cast<uint4*>(sm + OFF_AHI + r * PITCH + c * 16) = xh[gr * 16 + c];
            *reinterpret_cast<uint4*>(sm + OFF_ALO + r * PITCH + c * 16) = xl[gr * 16 + c];
        }
        const uint4* wh = reinterpret_cast<const uint4*>(g_wt2hi) + mat * 512;
        const uint4* wl = reinterpret_cast<const uint4*>(g_wt2lo) + mat * 512;
        for (int i = tid; i < 32 * 16; i += 256) {
            int r = i >> 4, c = i & 15;
            *reinterpret_cast<uint4*>(sm + OFF_BHI + r * PITCH + c * 16) = wh[r * 16 + c];
            *reinterpret_cast<uint4*>(sm + OFF_BLO + r * PITCH + c * 16) = wl[r * 16 + c];
        }
    }
    __syncthreads();

    float acc[4][4];
#pragma unroll
    for (int nt = 0; nt < 4; nt++)
#pragma unroll
        for (int q = 0; q < 4; q++) acc[nt][q] = 0.f;

    const int arow  = lane & 15;
    const int akoff = (lane >> 4) << 4;
    const int brow  = lane & 7;
    const int bkoff = ((lane >> 3) & 1) << 4;

#pragma unroll
    for (int ks = 0; ks < 8; ++ks) {
        const int kb = ks * 32;
        uint32_t ah[4], al[4];
        uint32_t addr = sbase + OFF_AHI + (wid * 16 + arow) * PITCH + kb + akoff;
        ldm_x4(ah, addr);
        ldm_x4(al, addr + (OFF_ALO - OFF_AHI));
        uint32_t bh[4][2], bo[4][2];
#pragma unroll
        for (int nt = 0; nt < 4; nt++) {
            uint32_t baddr = sbase + OFF_BHI + (nt * 8 + brow) * PITCH + kb + bkoff;
            ldm_x2(bh[nt], baddr);
            ldm_x2(bo[nt], baddr + (OFF_BLO - OFF_BHI));
        }
#pragma unroll
        for (int nt = 0; nt < 4; nt++) {
            mma_bf16(acc[nt], ah, bh[nt]);
            mma_bf16(acc[nt], ah, bo[nt]);
            mma_bf16(acc[nt], al, bh[nt]);
        }
    }

    const float* __restrict__ b = mat ? br : bl;
    float* __restrict__ C = mat ? g_gr2 : g_gl2;
    const int rql = lane >> 2;
    const int cql = (lane & 3) * 2;
    int r0 = row0 + wid * 16 + rql;
    int r1 = r0 + 8;
#pragma unroll
    for (int nt = 0; nt < 4; nt++) {
        int col = nt * 8 + cql;
        float2 bv = *reinterpret_cast<const float2*>(b + col);
        if (r0 < n) {
            float2 v = make_float2(acc[nt][0] + bv.x, acc[nt][1] + bv.y);
            *reinterpret_cast<float2*>(C + r0 * 32 + col) = v;
        }
        if (r1 < n) {
            float2 v = make_float2(acc[nt][2] + bv.x, acc[nt][3] + bv.y);
            *reinterpret_cast<float2*>(C + r1 * 32 + col) = v;
        }
    }
}

// ---------------- CSR scan (consumes + re-zeroes g_cnt) / atomic-free fill ----------
__global__ __launch_bounds__(1024) void csr_scan_kernel() {
    __shared__ unsigned s[1024];
    const int T = 1024;
    const int CH = (NN + T - 1) / T;
    int t = threadIdx.x;
    int base = t * CH;
    unsigned sum = 0;
    for (int i = 0; i < CH; i++) {
        int j = base + i;
        if (j < NN) sum += g_cnt[j];
    }
    s[t] = sum;
    __syncthreads();
    for (int off = 1; off < T; off <<= 1) {
        unsigned u = (t >= off) ? s[t - off] : 0u;
        __syncthreads();
        s[t] += u;
        __syncthreads();
    }
    unsigned run = s[t] - sum;
    for (int i = 0; i < CH; i++) {
        int j = base + i;
        if (j < NN) {
            unsigned c = g_cnt[j];
            g_cnt[j] = 0u;
            g_rowstart[j] = run;
            run += c;
        }
    }
    if (t == T - 1) g_rowstart[NN] = run;
}
__global__ void csr_fill_kernel(const int* __restrict__ ei) {
    int i = blockIdx.x * blockDim.x + threadIdx.x;
    if (i < EE) {
        int d = ei[EE + i];
        g_csrc[g_rowstart[d] + g_rank[i]] = ei[i];   // no atomics
    }
}

// ---------------- layer 1: fused attention aggregation (warp per dst, depth-2) -------
__global__ __launch_bounds__(256) void agg1_kernel(const float* __restrict__ att,
                                                   const float* __restrict__ bias) {
    const int lane = threadIdx.x & 31;
    const int d = blockIdx.x * (blockDim.x >> 5) + (threadIdx.x >> 5);
    if (d >= NN) return;

    const float4* __restrict__ gl4 = reinterpret_cast<const float4*>(g_gl1);
    const float4  grd = reinterpret_cast<const float4*>(g_gr1)[d * 32 + lane];
    const float4  at  = reinterpret_cast<const float4*>(att)[lane];

    float4 acc = make_float4(0.f, 0.f, 0.f, 0.f);
    float  den = 0.f;

    const unsigned start = g_rowstart[d];
    const unsigned deg   = g_rowstart[d + 1] - start;

    int s1 = (deg > 0) ? g_csrc[start]     : d;
    int s2 = (deg > 1) ? g_csrc[start + 1] : d;
    float4 gcur  = gl4[d  * 32 + lane];
    float4 gnext = gl4[s1 * 32 + lane];

    for (unsigned j = 0; j <= deg; ++j) {
        float4 gnn = gl4[s2 * 32 + lane];
        s2 = (j + 3 <= deg) ? g_csrc[start + j + 2] : d;

        float m0 = gcur.x + grd.x; m0 = fmaxf(m0, NEG * m0);
        float m1 = gcur.y + grd.y; m1 = fmaxf(m1, NEG * m1);
        float m2 = gcur.z + grd.z; m2 = fmaxf(m2, NEG * m2);
        float m3 = gcur.w + grd.w; m3 = fmaxf(m3, NEG * m3);
        float p = at.x * m0 + at.y * m1 + at.z * m2 + at.w * m3;
        p += __shfl_xor_sync(0xffffffffu, p, 1);
        p += __shfl_xor_sync(0xffffffffu, p, 2);
        p += __shfl_xor_sync(0xffffffffu, p, 4);
        float w = __expf(p);
        acc.x += w * gcur.x;
        acc.y += w * gcur.y;
        acc.z += w * gcur.z;
        acc.w += w * gcur.w;
        den += w;

        gcur = gnext;
        gnext = gnn;
    }

    const float inv = 1.f / den;
    const float4 b = reinterpret_cast<const float4*>(bias)[lane];
    float v0 = acc.x * inv + b.x; v0 = (v0 > 0.f) ? v0 : expm1f(v0);
    float v1 = acc.y * inv + b.y; v1 = (v1 > 0.f) ? v1 : expm1f(v1);
    float v2 = acc.z * inv + b.z; v2 = (v2 > 0.f) ? v2 : expm1f(v2);
    float v3 = acc.w * inv + b.w; v3 = (v3 > 0.f) ? v3 : expm1f(v3);

    float h0 = __bfloat162float(__float2bfloat16(v0));
    float h1 = __bfloat162float(__float2bfloat16(v1));
    float h2 = __bfloat162float(__float2bfloat16(v2));
    float h3 = __bfloat162float(__float2bfloat16(v3));
    uint2 hw, lw;
    hw.x = pack_bf2(v0, v1);
    hw.y = pack_bf2(v2, v3);
    lw.x = pack_bf2(v0 - h0, v1 - h1);
    lw.y = pack_bf2(v2 - h2, v3 - h3);
    reinterpret_cast<uint2*>(g_h1hi)[d * 32 + lane] = hw;
    reinterpret_cast<uint2*>(g_h1lo)[d * 32 + lane] = lw;
}

// ---------------- layer 2: aggregation, 4 dsts per warp (8 lanes / dst) -------------
__global__ __launch_bounds__(256) void agg2_kernel(const float* __restrict__ att,
                                                   const float* __restrict__ bias,
                                                   float* __restrict__ out) {
    const int lane = threadIdx.x & 31;
    const int grp  = lane >> 3;
    const int lg   = lane & 7;
    const int wid  = blockIdx.x * (blockDim.x >> 5) + (threadIdx.x >> 5);
    int d = wid * 4 + grp;
    const bool dvalid = (d < NN);
    if (d >= NN) d = NN - 1;

    const float4* __restrict__ gl4 = reinterpret_cast<const float4*>(g_gl2);
    const float4 grd  = reinterpret_cast<const float4*>(g_gr2)[d * 8 + lg];
    const float4 at   = reinterpret_cast<const float4*>(att)[lg];

    const unsigned start = g_rowstart[d];
    const unsigned deg   = dvalid ? (g_rowstart[d + 1] - start) : 0u;

    unsigned mdeg = deg;
#pragma unroll
    for (int off = 8; off < 32; off <<= 1) {
        unsigned o = __shfl_xor_sync(0xffffffffu, mdeg, off);
        mdeg = (o > mdeg) ? o : mdeg;
    }

    float4 acc = make_float4(0.f, 0.f, 0.f, 0.f);
    float  den = 0.f;

    int snext = (deg > 0) ? g_csrc[start] : d;
    float4 g = gl4[d * 8 + lg];

    for (unsigned j = 0; j <= mdeg; ++j) {
        float4 gc = g;
        int snn = (j + 2 <= deg) ? g_csrc[start + j + 1] : d;
        g = gl4[snext * 8 + lg];
        snext = snn;

        float m0 = gc.x + grd.x; m0 = fmaxf(m0, NEG * m0);
        float m1 = gc.y + grd.y; m1 = fmaxf(m1, NEG * m1);
        float m2 = gc.z + grd.z; m2 = fmaxf(m2, NEG * m2);
        float m3 = gc.w + grd.w; m3 = fmaxf(m3, NEG * m3);
        float p = at.x * m0 + at.y * m1 + at.z * m2 + at.w * m3;
        p += __shfl_xor_sync(0xffffffffu, p, 1);
        p += __shfl_xor_sync(0xffffffffu, p, 2);
        p += __shfl_xor_sync(0xffffffffu, p, 4);
        float w = (j <= deg) ? __expf(p) : 0.f;
        acc.x += w * gc.x;
        acc.y += w * gc.y;
        acc.z += w * gc.z;
        acc.w += w * gc.w;
        den += w;
    }

    if (dvalid) {
        const float inv = 1.f / den;
        const float4 b = reinterpret_cast<const float4*>(bias)[lg];
        reinterpret_cast<float4*>(out)[d * 8 + lg] =
            make_float4(acc.x * inv + b.x, acc.y * inv + b.y,
                        acc.z * inv + b.z, acc.w * inv + b.w);
    }
}

// ---------------- launch ----------------
extern "C" void kernel_launch(void* const* d_in, const int* in_sizes, int n_in,
                              void* d_out, int out_size) {
    const float* x    = (const float*)d_in[0];
    const int*   ei   = (const int*)d_in[1];
    const float* Wl1  = (const float*)d_in[2];
    const float* bl1  = (const float*)d_in[3];
    const float* Wr1  = (const float*)d_in[4];
    const float* br1  = (const float*)d_in[5];
    const float* att1 = (const float*)d_in[6];
    const float* bias1= (const float*)d_in[7];
    const float* Wl2  = (const float*)d_in[8];
    const float* bl2  = (const float*)d_in[9];
    const float* Wr2  = (const float*)d_in[10];
    const float* br2  = (const float*)d_in[11];
    const float* att2 = (const float*)d_in[12];
    const float* bias2= (const float*)d_in[13];
    float* out = (float*)d_out;

    const int smem1 = 2 * (64 * 272) + 2 * (128 * 272);   // 104448 -> 2 blocks/SM
    const int smem2 = 2 * (128 * 272) + 2 * (32 * 272);   // 87040  -> 2 blocks/SM
    cudaFuncSetAttribute(gemm1_mma_kernel,
                         cudaFuncAttributeMaxDynamicSharedMemorySize, smem1);
    cudaFuncSetAttribute(gemm2_mma_kernel,
                         cudaFuncAttributeMaxDynamicSharedMemorySize, smem2);

    // slot 1: fused prep; 2: gemm1; 3: scan; 4: fill (PROFILED — atomic-free);
    // 5: agg1; 6: gemm2; 7: agg2
    prep_kernel<<<dim3(6250, 2), 256>>>(x, ei, Wl1, Wr1, Wl2, Wr2);
    gemm1_mma_kernel<<<dim3((NN + 63) / 64, 2), 256, smem1>>>(NN, bl1, br1);
    csr_scan_kernel<<<1, 1024>>>();
    csr_fill_kernel<<<(EE + 255) / 256, 256>>>(ei);

    agg1_kernel<<<(NN + 7) / 8, 256>>>(att1, bias1);

    gemm2_mma_kernel<<<dim3((NN + 127) / 128, 2), 256, smem2>>>(NN, bl2, br2);
    agg2_kernel<<<(NN + 31) / 32, 256>>>(att2, bias2, out);
}